// round 17
// baseline (speedup 1.0000x reference)
#include <cuda_runtime.h>
#include <cuda_bf16.h>
#include <cstdint>
#include <cstddef>

// Problem constants
#define B_  2
#define H_  16
#define S_  4096
#define DH  64
#define E_  1024
#define SEG 1024
#define GK  1024
#define GK2 512            // u32 (bf16x2 pairs) per row

// ---------------------------------------------------------------------------
// Scratch (device globals — no runtime allocation allowed)
// Packed bf16x2 layout: [row][k/2], low 16 bits = even k.
// ---------------------------------------------------------------------------
__device__ uint32_t g_xs_hi[(size_t)B_ * S_ * GK2];
__device__ uint32_t g_xs_lo[(size_t)B_ * S_ * GK2];
__device__ uint32_t g_w1_hi[(size_t)3 * E_ * GK2];
__device__ uint32_t g_w1_lo[(size_t)3 * E_ * GK2];
__device__ uint32_t g_w2_hi[(size_t)E_ * GK2];
__device__ uint32_t g_w2_lo[(size_t)E_ * GK2];
__device__ uint32_t g_q_hi[(size_t)B_ * H_ * S_ * DH / 2];  // q pre-scaled 0.125
__device__ uint32_t g_q_lo[(size_t)B_ * H_ * S_ * DH / 2];
__device__ uint32_t g_k_hi[(size_t)B_ * H_ * S_ * DH / 2];
__device__ uint32_t g_k_lo[(size_t)B_ * H_ * S_ * DH / 2];
__device__ float    g_v   [(size_t)B_ * H_ * S_ * DH];      // tf32-rounded
__device__ uint32_t g_at_hi[(size_t)B_ * S_ * E_ / 2];
__device__ uint32_t g_at_lo[(size_t)B_ * S_ * E_ / 2];

// ---------------------------------------------------------------------------
// Helpers (sm_80-era PTX only — NO tcgen05: harness targets plain sm_103)
// ---------------------------------------------------------------------------
__device__ __forceinline__ uint32_t tf32_one(float v) {
    uint32_t u;
    asm("cvt.rna.tf32.f32 %0, %1;" : "=r"(u) : "f"(v));
    return u;
}
__device__ __forceinline__ float tf32f(float v) {
    uint32_t u;
    asm("cvt.rna.tf32.f32 %0, %1;" : "=r"(u) : "f"(v));
    return __uint_as_float(u);
}
__device__ __forceinline__ void bsplit(float v, float& hi, float& lo) {
    hi = __bfloat162float(__float2bfloat16(v));
    lo = v - hi;
}
// pack two floats as bf16x2; first arg -> low 16 bits (even k)
__device__ __forceinline__ uint32_t bf2(float lo_k, float hi_k) {
    uint32_t u;
    asm("cvt.rn.bf16x2.f32 %0, %1, %2;" : "=r"(u) : "f"(hi_k), "f"(lo_k));
    return u;
}
__device__ __forceinline__ void mma_bf16(float* c,
    uint32_t a0, uint32_t a1, uint32_t a2, uint32_t a3,
    uint32_t b0, uint32_t b1)
{
    asm volatile(
        "mma.sync.aligned.m16n8k16.row.col.f32.bf16.bf16.f32 "
        "{%0,%1,%2,%3}, {%4,%5,%6,%7}, {%8,%9}, {%0,%1,%2,%3};"
        : "+f"(c[0]), "+f"(c[1]), "+f"(c[2]), "+f"(c[3])
        : "r"(a0), "r"(a1), "r"(a2), "r"(a3), "r"(b0), "r"(b1));
}
__device__ __forceinline__ void mma_tf32(float* c,
    uint32_t a0, uint32_t a1, uint32_t a2, uint32_t a3,
    uint32_t b0, uint32_t b1)
{
    asm volatile(
        "mma.sync.aligned.m16n8k8.row.col.f32.tf32.tf32.f32 "
        "{%0,%1,%2,%3}, {%4,%5,%6,%7}, {%8,%9}, {%0,%1,%2,%3};"
        : "+f"(c[0]), "+f"(c[1]), "+f"(c[2]), "+f"(c[3])
        : "r"(a0), "r"(a1), "r"(a2), "r"(a3), "r"(b0), "r"(b1));
}

// ---------------------------------------------------------------------------
// Pre-split: fp32 -> packed bf16x2 hi/lo.  which: 0=x, 1=w_qkv, 2=w_out
// ---------------------------------------------------------------------------
__global__ void split_kernel(const float4* __restrict__ src, int n4, int which)
{
    int i = blockIdx.x * blockDim.x + threadIdx.x;
    if (i >= n4) return;
    uint2* hi = (which == 0) ? (uint2*)g_xs_hi : (which == 1) ? (uint2*)g_w1_hi
                                                              : (uint2*)g_w2_hi;
    uint2* lo = (which == 0) ? (uint2*)g_xs_lo : (which == 1) ? (uint2*)g_w1_lo
                                                              : (uint2*)g_w2_lo;
    float4 v = src[i];
    float hx, lx, hy, ly, hz, lz, hw, lw;
    bsplit(v.x, hx, lx); bsplit(v.y, hy, ly);
    bsplit(v.z, hz, lz); bsplit(v.w, hw, lw);
    hi[i] = make_uint2(bf2(hx, hy), bf2(hz, hw));
    lo[i] = make_uint2(bf2(lx, ly), bf2(lz, lw));
}

// ---------------------------------------------------------------------------
// 3xBF16 GEMM on pre-split operands. BM=BN=128, BK=16, 8 warps 2x4.
// Frag strides 36/144 (A), 36/72 (B): 16B-aligned bases -> pure
// ldg.128 + STS.128 copy loop, zero conversion math.
// mode 0: A=g_xs B=g_w1, epilogue emits split q (x0.125) / split k / tf32 v.
// mode 1: A=g_at B=g_w2, epilogue stores fp32 C.
// ---------------------------------------------------------------------------
#define AHI 0
#define ALO 1152
#define BHI 2304
#define BLO 3456
#define BUFU 4608
#define GEMM_SMEM (2 * BUFU * 4)     // 36864 bytes

__device__ __forceinline__ void ldg_packed(uint4* r,
    const uint32_t* Ahi, const uint32_t* Alo,
    const uint32_t* Bhi, const uint32_t* Blo,
    int m0, int n0, int c, int tid)
{
    if (tid < 128) {
        const uint32_t* ph = Ahi + (size_t)(m0 + tid) * GK2 + c * 8;
        const uint32_t* pl = Alo + (size_t)(m0 + tid) * GK2 + c * 8;
        r[0] = *(const uint4*)(ph);     r[1] = *(const uint4*)(ph + 4);
        r[2] = *(const uint4*)(pl);     r[3] = *(const uint4*)(pl + 4);
    } else {
        const uint32_t* ph = Bhi + (size_t)(n0 + tid - 128) * GK2 + c * 8;
        const uint32_t* pl = Blo + (size_t)(n0 + tid - 128) * GK2 + c * 8;
        r[0] = *(const uint4*)(ph);     r[1] = *(const uint4*)(ph + 4);
        r[2] = *(const uint4*)(pl);     r[3] = *(const uint4*)(pl + 4);
    }
}
__device__ __forceinline__ void sts_packed(uint32_t* smu, const uint4* r, int tid)
{
    if (tid < 128) {
        int base = (tid >> 4) * 144 + ((tid & 15) >> 3) * 36 + (tid & 7) * 4;
        *(uint4*)(smu + AHI + base)      = r[0];
        *(uint4*)(smu + AHI + base + 72) = r[1];
        *(uint4*)(smu + ALO + base)      = r[2];
        *(uint4*)(smu + ALO + base + 72) = r[3];
    } else {
        int t2 = tid - 128;
        int base = (t2 >> 3) * 72 + (t2 & 7) * 4;
        *(uint4*)(smu + BHI + base)      = r[0];
        *(uint4*)(smu + BHI + base + 36) = r[1];
        *(uint4*)(smu + BLO + base)      = r[2];
        *(uint4*)(smu + BLO + base + 36) = r[3];
    }
}

__global__ __launch_bounds__(256, 2) void gemm_bf16_kernel(
    const float* __restrict__ bias, float* __restrict__ C, int N, int mode)
{
    extern __shared__ char dynsm[];
    uint32_t* smu = (uint32_t*)dynsm;

    const uint32_t *Ahi, *Alo, *Bhi, *Blo;
    if (mode == 0) { Ahi = g_xs_hi; Alo = g_xs_lo; Bhi = g_w1_hi; Blo = g_w1_lo; }
    else           { Ahi = g_at_hi; Alo = g_at_lo; Bhi = g_w2_hi; Blo = g_w2_lo; }

    const int tid  = threadIdx.x;
    const int lane = tid & 31;
    const int wid  = tid >> 5;
    const int wr   = wid >> 2;
    const int wc   = wid & 3;
    const int m0 = blockIdx.y << 7;
    const int n0 = blockIdx.x << 7;

    float acc[4][4][4];
#pragma unroll
    for (int u = 0; u < 4; u++)
#pragma unroll
        for (int t = 0; t < 4; t++)
#pragma unroll
            for (int j = 0; j < 4; j++) acc[u][t][j] = 0.f;

    uint4 cr[4];
    ldg_packed(cr, Ahi, Alo, Bhi, Blo, m0, n0, 0, tid);
    sts_packed(smu, cr, tid);
    __syncthreads();

    int p = 0;
    for (int c = 1; c <= GK / 16; c++) {
        if (c < GK / 16) ldg_packed(cr, Ahi, Alo, Bhi, Blo, m0, n0, c, tid);

        const uint32_t* buf = smu + p * BUFU;
        uint32_t bh[4][2], bl[4][2];
#pragma unroll
        for (int t = 0; t < 4; t++) {
            int bi = (wc * 4 + t) * 72 + lane;
            bh[t][0] = buf[BHI + bi];   bh[t][1] = buf[BHI + bi + 36];
            bl[t][0] = buf[BLO + bi];   bl[t][1] = buf[BLO + bi + 36];
        }
#pragma unroll
        for (int u = 0; u < 4; u++) {
            int ai = (wr * 4 + u) * 144 + lane;
            uint32_t ah[4], al[4];
#pragma unroll
            for (int rg = 0; rg < 4; rg++) {
                ah[rg] = buf[AHI + ai + rg * 36];
                al[rg] = buf[ALO + ai + rg * 36];
            }
#pragma unroll
            for (int t = 0; t < 4; t++) {
                mma_bf16(acc[u][t], ah[0], ah[1], ah[2], ah[3], bh[t][0], bh[t][1]);
                mma_bf16(acc[u][t], ah[0], ah[1], ah[2], ah[3], bl[t][0], bl[t][1]);
                mma_bf16(acc[u][t], al[0], al[1], al[2], al[3], bh[t][0], bh[t][1]);
            }
        }

        if (c < GK / 16) {
            p ^= 1;
            sts_packed(smu + p * BUFU, cr, tid);
            __syncthreads();
        }
    }

    const int grp = lane >> 2;
    const int tig = lane & 3;
#pragma unroll
    for (int u = 0; u < 4; u++) {
#pragma unroll
        for (int part = 0; part < 2; part++) {
            int m = m0 + wr * 64 + u * 16 + grp + part * 8;
            int bb = m >> 12;
            int s  = m & 4095;
#pragma unroll
            for (int t = 0; t < 4; t++) {
                int n = n0 + wc * 32 + t * 8 + tig * 2;
                float2 bv = *(const float2*)(bias + n);
                float2 r;
                r.x = acc[u][t][part * 2 + 0] + bv.x;
                r.y = acc[u][t][part * 2 + 1] + bv.y;
                if (mode == 0) {
                    int tt = n >> 10;
                    int hh = (n >> 6) & 15;
                    int d  = n & 63;
                    size_t rowoff = ((size_t)bb * H_ + hh) * S_ + s;
                    if (tt == 2) {
                        // V: tf32-round, store float2
                        r.x = tf32f(r.x); r.y = tf32f(r.y);
                        *(float2*)&g_v[rowoff * DH + d] = r;
                    } else {
                        float sc = (tt == 0) ? 0.125f : 1.0f;
                        float hx, lx, hy, ly;
                        bsplit(r.x * sc, hx, lx);
                        bsplit(r.y * sc, hy, ly);
                        size_t pi = rowoff * (DH / 2) + (d >> 1);
                        if (tt == 0) { g_q_hi[pi] = bf2(hx, hy); g_q_lo[pi] = bf2(lx, ly); }
                        else         { g_k_hi[pi] = bf2(hx, hy); g_k_lo[pi] = bf2(lx, ly); }
                    }
                } else {
                    *(float2*)&C[(size_t)m * N + n] = r;
                }
            }
        }
    }
}

// ---------------------------------------------------------------------------
// MMA flash attention on pre-split operands. 128 thr / 4 warps per
// (b, h, 64-query tile). S = 3xBF16 k16; PV = single tf32 k8.
// Loaders are pure ldg.128 + STS.128/STS.32 copies (no conversion).
// SMEM (u32): QHI/QLO 2304 ea; KHI/KLO 2304 ea; VF 4224; P 4352.
// ---------------------------------------------------------------------------
#define AT_QHI 0
#define AT_QLO 2304
#define AT_KHI 4608
#define AT_KLO 6912
#define AT_VF  9216
#define AT_P   13440
#define ATT_SMEM2 ((13440 + 64 * 68) * 4)   // 71168 bytes

__global__ __launch_bounds__(128, 3) void attn_mma_kernel()
{
    extern __shared__ char dynsm[];
    uint32_t* smw = (uint32_t*)dynsm;

    const int tid  = threadIdx.x;
    const int lane = tid & 31;
    const int w    = tid >> 5;
    const int g    = lane >> 2;
    const int q4   = lane & 3;
    const int qt = blockIdx.x;
    const int h  = blockIdx.y;
    const int b  = blockIdx.z;
    const int s0 = qt << 6;
    const int kbase = s0 & ~(SEG - 1);
    const size_t rowoff = ((size_t)b * H_ + h) * S_;

    // ---- Q: pure copy into k16 A-frags (pre-scaled/split by producer) ----
    // 64 rows x 8 uint4 per array = 512 uint4; 128 threads x 4 iters.
    {
        const uint32_t* qh = g_q_hi + (rowoff + s0) * (DH / 2);
        const uint32_t* ql = g_q_lo + (rowoff + s0) * (DH / 2);
        int qrow = tid & 63;
        int dq0  = tid >> 6;
#pragma unroll
        for (int ii = 0; ii < 4; ii++) {
            int dq = dq0 + ii * 2;          // covers 0..7
            uint4 vh = *(const uint4*)(qh + qrow * 32 + dq * 4);
            uint4 vl = *(const uint4*)(ql + qrow * 32 + dq * 4);
            int base = ((qrow >> 4) * 4 + (dq >> 1)) * 144
                     + (((qrow & 15) >> 3) + 2 * (dq & 1)) * 36 + (qrow & 7) * 4;
            *(uint4*)(smw + AT_QHI + base) = vh;
            *(uint4*)(smw + AT_QLO + base) = vl;
        }
    }

    float o[8][4];
#pragma unroll
    for (int dt = 0; dt < 8; dt++)
#pragma unroll
        for (int j = 0; j < 4; j++) o[dt][j] = 0.f;
    float m0 = -1e30f, m1 = -1e30f, l0 = 0.f, l1 = 0.f;

    for (int kt = 0; kt < 16; kt++) {
        __syncthreads();   // prev iteration's K/V readers done

        // ---- K copy (k16 B-frags) + V copy (tf32 k8 B-frags) ----
        {
            const uint32_t* kh = g_k_hi + (rowoff + kbase + kt * 64) * (DH / 2);
            const uint32_t* kl = g_k_lo + (rowoff + kbase + kt * 64) * (DH / 2);
            const float*    vp = g_v + (rowoff + kbase + kt * 64) * DH;
            int krow = tid & 63;
            int dq0  = tid >> 6;
#pragma unroll
            for (int ii = 0; ii < 4; ii++) {
                int dq = dq0 + ii * 2;      // covers 0..7
                uint4 vh = *(const uint4*)(kh + krow * 32 + dq * 4);
                uint4 vl = *(const uint4*)(kl + krow * 32 + dq * 4);
                int base = ((dq >> 1) * 8 + (krow >> 3)) * 72
                         + (dq & 1) * 36 + (krow & 7) * 4;
                *(uint4*)(smw + AT_KHI + base) = vh;
                *(uint4*)(smw + AT_KLO + base) = vl;
            }
#pragma unroll
            for (int i = 0; i < 8; i++) {
                int idx = tid + i * 128;
                int key = idx >> 4;
                int d0  = (idx & 15) << 2;
                float4 vv = *(const float4*)(vp + key * DH + d0);
                int baseV = (((key >> 3) * 8 + (d0 >> 3)) * 2 + ((key & 7) >> 2)) * 33
                            + (d0 & 7) * 4 + (key & 3);
                smw[AT_VF + baseV +  0] = __float_as_uint(vv.x);
                smw[AT_VF + baseV +  4] = __float_as_uint(vv.y);
                smw[AT_VF + baseV +  8] = __float_as_uint(vv.z);
                smw[AT_VF + baseV + 12] = __float_as_uint(vv.w);
            }
        }
        __syncthreads();

        // ---- S = Q K^T (3xBF16) ----
        float sacc[8][4];
#pragma unroll
        for (int nt = 0; nt < 8; nt++)
#pragma unroll
            for (int j = 0; j < 4; j++) sacc[nt][j] = 0.f;

#pragma unroll
        for (int ks = 0; ks < 4; ks++) {
            int ab = (w * 4 + ks) * 144 + lane;
            uint32_t ah[4], al[4];
#pragma unroll
            for (int rg = 0; rg < 4; rg++) {
                ah[rg] = smw[AT_QHI + ab + rg * 36];
                al[rg] = smw[AT_QLO + ab + rg * 36];
            }
#pragma unroll
            for (int nt = 0; nt < 8; nt++) {
                int bb2 = (ks * 8 + nt) * 72 + lane;
                uint32_t bh0 = smw[AT_KHI + bb2], bh1 = smw[AT_KHI + bb2 + 36];
                uint32_t bl0 = smw[AT_KLO + bb2], bl1 = smw[AT_KLO + bb2 + 36];
                mma_bf16(sacc[nt], ah[0], ah[1], ah[2], ah[3], bh0, bh1);
                mma_bf16(sacc[nt], ah[0], ah[1], ah[2], ah[3], bl0, bl1);
                mma_bf16(sacc[nt], al[0], al[1], al[2], al[3], bh0, bh1);
            }
        }

        // ---- Online softmax (rows g and g+8; reduce across quad lanes) ----
        float rmx0 = -1e30f, rmx1 = -1e30f;
#pragma unroll
        for (int nt = 0; nt < 8; nt++) {
            rmx0 = fmaxf(rmx0, fmaxf(sacc[nt][0], sacc[nt][1]));
            rmx1 = fmaxf(rmx1, fmaxf(sacc[nt][2], sacc[nt][3]));
        }
        rmx0 = fmaxf(rmx0, __shfl_xor_sync(0xffffffffu, rmx0, 1));
        rmx0 = fmaxf(rmx0, __shfl_xor_sync(0xffffffffu, rmx0, 2));
        rmx1 = fmaxf(rmx1, __shfl_xor_sync(0xffffffffu, rmx1, 1));
        rmx1 = fmaxf(rmx1, __shfl_xor_sync(0xffffffffu, rmx1, 2));
        float nm0 = fmaxf(m0, rmx0), nm1 = fmaxf(m1, rmx1);
        float c0 = __expf(m0 - nm0), c1 = __expf(m1 - nm1);
        float rs0 = 0.f, rs1 = 0.f;
        const int prow0 = AT_P + (w * 16 + g) * 68;
        const int prow1 = prow0 + 8 * 68;
#pragma unroll
        for (int nt = 0; nt < 8; nt++) {
            float p0 = __expf(sacc[nt][0] - nm0);
            float p1 = __expf(sacc[nt][1] - nm0);
            float p2 = __expf(sacc[nt][2] - nm1);
            float p3 = __expf(sacc[nt][3] - nm1);
            rs0 += p0 + p1;
            rs1 += p2 + p3;
            int col = nt * 8 + q4 * 2;
            smw[prow0 + col]     = tf32_one(p0);
            smw[prow0 + col + 1] = tf32_one(p1);
            smw[prow1 + col]     = tf32_one(p2);
            smw[prow1 + col + 1] = tf32_one(p3);
        }
        rs0 += __shfl_xor_sync(0xffffffffu, rs0, 1);
        rs0 += __shfl_xor_sync(0xffffffffu, rs0, 2);
        rs1 += __shfl_xor_sync(0xffffffffu, rs1, 1);
        rs1 += __shfl_xor_sync(0xffffffffu, rs1, 2);
        l0 = l0 * c0 + rs0;  m0 = nm0;
        l1 = l1 * c1 + rs1;  m1 = nm1;
#pragma unroll
        for (int dt = 0; dt < 8; dt++) {
            o[dt][0] *= c0; o[dt][1] *= c0;
            o[dt][2] *= c1; o[dt][3] *= c1;
        }
        __syncwarp();   // P is warp-local: order writes before A-frag reads

        // ---- O += P V  (tf32) ----
#pragma unroll
        for (int ks = 0; ks < 8; ks++) {
            int pa = AT_P + (w * 16 + g) * 68 + ks * 8 + q4;
            uint32_t a0 = smw[pa];
            uint32_t a1 = smw[pa + 8 * 68];
            uint32_t a2 = smw[pa + 4];
            uint32_t a3 = smw[pa + 8 * 68 + 4];
#pragma unroll
            for (int dt = 0; dt < 8; dt++) {
                int vb = AT_VF + ((ks * 8 + dt) * 2) * 33 + lane;
                mma_tf32(o[dt], a0, a1, a2, a3, smw[vb], smw[vb + 33]);
            }
        }
    }

    // ---- Normalize, emit pre-split attn output for GEMM2's A ----
    float inv0 = 1.f / l0, inv1 = 1.f / l1;
    const int row0 = s0 + w * 16 + g;
#pragma unroll
    for (int dt = 0; dt < 8; dt++) {
        int col = dt * 8 + q4 * 2;
        float x0 = o[dt][0] * inv0, y0 = o[dt][1] * inv0;
        float x1 = o[dt][2] * inv1, y1 = o[dt][3] * inv1;
        float hx, lx, hy, ly;
        size_t pi0 = ((size_t)b * S_ + row0) * (E_ / 2) + ((h * DH + col) >> 1);
        size_t pi1 = pi0 + 8 * (E_ / 2);
        bsplit(x0, hx, lx); bsplit(y0, hy, ly);
        g_at_hi[pi0] = bf2(hx, hy);  g_at_lo[pi0] = bf2(lx, ly);
        bsplit(x1, hx, lx); bsplit(y1, hy, ly);
        g_at_hi[pi1] = bf2(hx, hy);  g_at_lo[pi1] = bf2(lx, ly);
    }
}

// ---------------------------------------------------------------------------
// kernel_launch: split x/w -> gemm(qkv) -> attention -> gemm(out)
// ---------------------------------------------------------------------------
extern "C" void kernel_launch(void* const* d_in, const int* in_sizes, int n_in,
                              void* d_out, int out_size)
{
    (void)in_sizes; (void)n_in; (void)out_size;
    const float* x     = (const float*)d_in[0];
    const float* w_qkv = (const float*)d_in[1];
    const float* b_qkv = (const float*)d_in[2];
    const float* w_out = (const float*)d_in[3];
    const float* b_out = (const float*)d_in[4];
    float* out = (float*)d_out;

    cudaFuncSetAttribute(gemm_bf16_kernel,
                         cudaFuncAttributeMaxDynamicSharedMemorySize, GEMM_SMEM);
    cudaFuncSetAttribute(attn_mma_kernel,
                         cudaFuncAttributeMaxDynamicSharedMemorySize, ATT_SMEM2);

    // 0) Pre-split inputs to packed bf16x2 hi/lo
    {
        int n4x = B_ * S_ * GK / 4;          // 2097152
        int n4w1 = 3 * E_ * GK / 4;          // 786432
        int n4w2 = E_ * GK / 4;              // 262144
        split_kernel<<<(n4x  + 255) / 256, 256>>>((const float4*)x,     n4x,  0);
        split_kernel<<<(n4w1 + 255) / 256, 256>>>((const float4*)w_qkv, n4w1, 1);
        split_kernel<<<(n4w2 + 255) / 256, 256>>>((const float4*)w_out, n4w2, 2);
    }
    // 1) QKV projection -> split q (x0.125) / split k / tf32 v
    {
        dim3 grid(3 * E_ / 128, (B_ * S_) / 128);   // (24, 64)
        gemm_bf16_kernel<<<grid, 256, GEMM_SMEM>>>(b_qkv, nullptr, 3 * E_, 0);
    }
    // 2) Segmented attention (bf16 S + tf32 PV) -> split attn
    {
        dim3 grid(S_ / 64, H_, B_);                 // (64, 16, 2)
        attn_mma_kernel<<<grid, 128, ATT_SMEM2>>>();
    }
    // 3) Output projection -> d_out
    {
        dim3 grid(E_ / 128, (B_ * S_) / 128);       // (8, 64)
        gemm_bf16_kernel<<<grid, 256, GEMM_SMEM>>>(b_out, out, E_, 1);
    }
}